// round 11
// baseline (speedup 1.0000x reference)
#include <cuda_runtime.h>
#include <cuda_bf16.h>

#define LGT      16
#define NROWS    4096
#define DCOLS    16000          // CLASSNUM * LGT
#define NWORKERS (152 * 8)      // 1216 persistent CTAs; 8/SM on 152 SMs

__device__ float        g_acc = 0.0f;
__device__ unsigned int g_cnt = 0u;

__global__ __launch_bounds__(256, 8)
void rvsml_loss_kernel(const float* __restrict__ inputs,
                       const float* __restrict__ labels,
                       float* __restrict__ out) {
    const int tid  = threadIdx.x;
    const int wid  = tid >> 5;
    const int lane = tid & 31;

    float total = 0.0f;   // per-thread running contribution

    // Static interleaved rows (3-4 per CTA), zero-sync mainloop.
    for (int row = blockIdx.x; row < NROWS; row += NWORKERS) {
        // ---- Labels (warp-local broadcast; L1-hot) ----
        const float* lab = labels + row * (LGT + 1);
        float lv = (lane <= LGT) ? __ldg(lab + lane) : 0.0f;
        const int   c = (int)__shfl_sync(0xFFFFFFFFu, lv, LGT);
        const float w = (lane < LGT) ? lv : 0.0f;
        float W = w;
        #pragma unroll
        for (int off = 16; off > 0; off >>= 1)
            W += __shfl_xor_sync(0xFFFFFFFFu, W, off);

        // ---- Stream the row: block-thread-strided, L1-bypass (.cg),
        //      fixed trip count (15*256 = 3840 vecs) + 160-vec remainder ----
        const float4* rowp =
            reinterpret_cast<const float4*>(inputs + (size_t)row * DCOLS);
        float sq = 0.0f;
        {
            int i = tid;
            #pragma unroll 5
            for (int it = 0; it < 15; it++, i += 256) {
                float4 v = __ldcg(rowp + i);
                sq = fmaf(v.x, v.x, sq);
                sq = fmaf(v.y, v.y, sq);
                sq = fmaf(v.z, v.z, sq);
                sq = fmaf(v.w, v.w, sq);
            }
            if (tid < 160) {                     // 4000 - 3840
                float4 v = __ldcg(rowp + 3840 + tid);
                sq = fmaf(v.x, v.x, sq);
                sq = fmaf(v.y, v.y, sq);
                sq = fmaf(v.z, v.z, sq);
                sq = fmaf(v.w, v.w, sq);
            }
        }
        // Linearity: fold W_i * (thread's partial sq); no row reduction.
        total = fmaf(W, sq, total);

        // ---- Gather term, once per row (warp 0 lanes 0..15; L2-hot) ----
        if (wid == 0 && lane < LGT) {
            const float g = __ldg(inputs + (size_t)row * DCOLS + c * LGT + lane);
            total = fmaf(w, 1.0f - 2.0f * g, total);
        }
    }

    // ---- Epilogue: one block reduce + one global atomic per CTA ----
    __shared__ float warp_sums[8];
    #pragma unroll
    for (int off = 16; off > 0; off >>= 1)
        total += __shfl_xor_sync(0xFFFFFFFFu, total, off);
    if (lane == 0) warp_sums[wid] = total;
    __syncthreads();

    if (tid < 32) {
        float v = (tid < 8) ? warp_sums[tid] : 0.0f;
        #pragma unroll
        for (int off = 4; off > 0; off >>= 1)
            v += __shfl_xor_sync(0xFFFFFFFFu, v, off);

        if (tid == 0) {
            atomicAdd(&g_acc, v);
            __threadfence();
            const unsigned done = atomicAdd(&g_cnt, 1u);
            if (done == NWORKERS - 1) {
                // All contributions visible (each CTA fenced before its
                // counter increment). Read + reset for the next graph replay.
                const float t = atomicExch(&g_acc, 0.0f);
                out[0] = t * (1.0f / (float)NROWS);
                g_cnt = 0u;
                __threadfence();
            }
        }
    }
}

extern "C" void kernel_launch(void* const* d_in, const int* in_sizes, int n_in,
                              void* d_out, int out_size) {
    const float* inputs = (const float*)d_in[0];
    const float* labels = (const float*)d_in[1];
    float* out = (float*)d_out;

    rvsml_loss_kernel<<<NWORKERS, 256>>>(inputs, labels, out);
}

// round 12
// speedup vs baseline: 1.0142x; 1.0142x over previous
#include <cuda_runtime.h>
#include <cuda_bf16.h>

#define LGT      16
#define NROWS    4096
#define DCOLS    16000          // CLASSNUM * LGT
#define NWORKERS (152 * 8)      // 1216 persistent CTAs; 8/SM on 152 SMs

__device__ float        g_acc = 0.0f;
__device__ unsigned int g_cnt = 0u;

__global__ __launch_bounds__(256, 8)
void rvsml_loss_kernel(const float* __restrict__ inputs,
                       const float* __restrict__ labels,
                       float* __restrict__ out) {
    const int tid  = threadIdx.x;
    const int wid  = tid >> 5;
    const int lane = tid & 31;

    float total = 0.0f;   // per-thread running contribution

    // Static interleaved rows (3-4 per CTA), zero-sync mainloop:
    // no barriers, no atomics, no smem until the epilogue.
    for (int row = blockIdx.x; row < NROWS; row += NWORKERS) {
        // ---- Labels (warp-local broadcast; L1-hot) ----
        const float* lab = labels + row * (LGT + 1);
        float lv = (lane <= LGT) ? __ldg(lab + lane) : 0.0f;
        const int   c = (int)__shfl_sync(0xFFFFFFFFu, lv, LGT);
        const float w = (lane < LGT) ? lv : 0.0f;
        float W = w;
        #pragma unroll
        for (int off = 16; off > 0; off >>= 1)
            W += __shfl_xor_sync(0xFFFFFFFFu, W, off);

        // ---- Stream the row: block-thread-strided, default cached loads
        //      (both .cs and .cg hints measured worse on sm_103a) ----
        const float4* rowp =
            reinterpret_cast<const float4*>(inputs + (size_t)row * DCOLS);
        float sq = 0.0f;
        #pragma unroll 4
        for (int i = tid; i < DCOLS / 4; i += 256) {
            float4 v = rowp[i];
            sq = fmaf(v.x, v.x, sq);
            sq = fmaf(v.y, v.y, sq);
            sq = fmaf(v.z, v.z, sq);
            sq = fmaf(v.w, v.w, sq);
        }
        // Linearity: fold W_i * (thread's partial sq); no row reduction.
        total = fmaf(W, sq, total);

        // ---- Gather term, once per row (warp 0 lanes 0..15; L2-hot) ----
        if (wid == 0 && lane < LGT) {
            const float g = __ldg(inputs + (size_t)row * DCOLS + c * LGT + lane);
            total = fmaf(w, 1.0f - 2.0f * g, total);
        }
    }

    // ---- Epilogue: one block reduce + one global atomic per CTA ----
    __shared__ float warp_sums[8];
    #pragma unroll
    for (int off = 16; off > 0; off >>= 1)
        total += __shfl_xor_sync(0xFFFFFFFFu, total, off);
    if (lane == 0) warp_sums[wid] = total;
    __syncthreads();

    if (tid < 32) {
        float v = (tid < 8) ? warp_sums[tid] : 0.0f;
        #pragma unroll
        for (int off = 4; off > 0; off >>= 1)
            v += __shfl_xor_sync(0xFFFFFFFFu, v, off);

        if (tid == 0) {
            atomicAdd(&g_acc, v);
            __threadfence();
            const unsigned done = atomicAdd(&g_cnt, 1u);
            if (done == NWORKERS - 1) {
                // All contributions visible (each CTA fenced before its
                // counter increment). Read + reset for the next graph replay.
                const float t = atomicExch(&g_acc, 0.0f);
                out[0] = t * (1.0f / (float)NROWS);
                g_cnt = 0u;
                __threadfence();
            }
        }
    }
}

extern "C" void kernel_launch(void* const* d_in, const int* in_sizes, int n_in,
                              void* d_out, int out_size) {
    const float* inputs = (const float*)d_in[0];
    const float* labels = (const float*)d_in[1];
    float* out = (float*)d_out;

    rvsml_loss_kernel<<<NWORKERS, 256>>>(inputs, labels, out);
}

// round 13
// speedup vs baseline: 1.0447x; 1.0300x over previous
#include <cuda_runtime.h>
#include <cuda_bf16.h>

#define LGT      16
#define NROWS    4096
#define DCOLS    16000          // CLASSNUM * LGT
#define NTHREADS 512
#define NWORKERS (152 * 4)      // 608 persistent CTAs; 4/SM (occ capped by regs)

__device__ float        g_acc = 0.0f;
__device__ unsigned int g_cnt = 0u;

__global__ __launch_bounds__(NTHREADS, 4)
void rvsml_loss_kernel(const float* __restrict__ inputs,
                       const float* __restrict__ labels,
                       float* __restrict__ out) {
    const int tid  = threadIdx.x;
    const int wid  = tid >> 5;
    const int lane = tid & 31;

    float total = 0.0f;   // per-thread running contribution

    // Static interleaved rows (~6.7 per CTA), zero-sync mainloop.
    // block=512 @ occ 4: same 2048 threads/SM as before, but only 4
    // concurrent row streams per SM (608 chip-wide vs 1216) -> better
    // DRAM page locality at unchanged latency-hiding parallelism.
    for (int row = blockIdx.x; row < NROWS; row += NWORKERS) {
        // ---- Labels (warp-local broadcast; L1-hot) ----
        const float* lab = labels + row * (LGT + 1);
        float lv = (lane <= LGT) ? __ldg(lab + lane) : 0.0f;
        const int   c = (int)__shfl_sync(0xFFFFFFFFu, lv, LGT);
        const float w = (lane < LGT) ? lv : 0.0f;
        float W = w;
        #pragma unroll
        for (int off = 16; off > 0; off >>= 1)
            W += __shfl_xor_sync(0xFFFFFFFFu, W, off);

        // ---- Stream the row: block-thread-strided, default cached loads ----
        const float4* rowp =
            reinterpret_cast<const float4*>(inputs + (size_t)row * DCOLS);
        float sq = 0.0f;
        #pragma unroll 4
        for (int i = tid; i < DCOLS / 4; i += NTHREADS) {
            float4 v = rowp[i];
            sq = fmaf(v.x, v.x, sq);
            sq = fmaf(v.y, v.y, sq);
            sq = fmaf(v.z, v.z, sq);
            sq = fmaf(v.w, v.w, sq);
        }
        // Linearity: fold W_i * (thread's partial sq); no row reduction.
        total = fmaf(W, sq, total);

        // ---- Gather term, once per row (warp 0 lanes 0..15; L2-hot) ----
        if (wid == 0 && lane < LGT) {
            const float g = __ldg(inputs + (size_t)row * DCOLS + c * LGT + lane);
            total = fmaf(w, 1.0f - 2.0f * g, total);
        }
    }

    // ---- Epilogue: one block reduce + one global atomic per CTA ----
    __shared__ float warp_sums[NTHREADS / 32];
    #pragma unroll
    for (int off = 16; off > 0; off >>= 1)
        total += __shfl_xor_sync(0xFFFFFFFFu, total, off);
    if (lane == 0) warp_sums[wid] = total;
    __syncthreads();

    if (tid < 32) {
        float v = (tid < NTHREADS / 32) ? warp_sums[tid] : 0.0f;
        #pragma unroll
        for (int off = 8; off > 0; off >>= 1)
            v += __shfl_xor_sync(0xFFFFFFFFu, v, off);

        if (tid == 0) {
            atomicAdd(&g_acc, v);
            __threadfence();
            const unsigned done = atomicAdd(&g_cnt, 1u);
            if (done == NWORKERS - 1) {
                // All contributions visible (each CTA fenced before its
                // counter increment). Read + reset for the next graph replay.
                const float t = atomicExch(&g_acc, 0.0f);
                out[0] = t * (1.0f / (float)NROWS);
                g_cnt = 0u;
                __threadfence();
            }
        }
    }
}

extern "C" void kernel_launch(void* const* d_in, const int* in_sizes, int n_in,
                              void* d_out, int out_size) {
    const float* inputs = (const float*)d_in[0];
    const float* labels = (const float*)d_in[1];
    float* out = (float*)d_out;

    rvsml_loss_kernel<<<NWORKERS, NTHREADS>>>(inputs, labels, out);
}

// round 14
// speedup vs baseline: 1.0936x; 1.0468x over previous
#include <cuda_runtime.h>
#include <cuda_bf16.h>

#define LGT      16
#define NROWS    4096
#define DCOLS    16000          // CLASSNUM * LGT
#define NTHREADS 1024
#define NWORKERS (152 * 2)      // 304 persistent CTAs; 2/SM (regs cap 32)

__device__ float        g_acc = 0.0f;
__device__ unsigned int g_cnt = 0u;

__global__ __launch_bounds__(NTHREADS, 2)
void rvsml_loss_kernel(const float* __restrict__ inputs,
                       const float* __restrict__ labels,
                       float* __restrict__ out) {
    const int tid  = threadIdx.x;
    const int wid  = tid >> 5;
    const int lane = tid & 31;

    float total = 0.0f;   // per-thread running contribution

    // Static interleaved rows (~13.5 per CTA), zero-sync mainloop.
    // block=1024 @ occ 2: 2048 threads/SM as before, but only 2 row
    // streams per SM (304 chip-wide). Each iteration's frontier is a
    // contiguous 16KB span -> maximal DRAM open-row locality.
    for (int row = blockIdx.x; row < NROWS; row += NWORKERS) {
        // ---- Labels (warp-local broadcast; L1-hot) ----
        const float* lab = labels + row * (LGT + 1);
        float lv = (lane <= LGT) ? __ldg(lab + lane) : 0.0f;
        const int   c = (int)__shfl_sync(0xFFFFFFFFu, lv, LGT);
        const float w = (lane < LGT) ? lv : 0.0f;
        float W = w;
        #pragma unroll
        for (int off = 16; off > 0; off >>= 1)
            W += __shfl_xor_sync(0xFFFFFFFFu, W, off);

        // ---- Stream the row: block-thread-strided, default cached loads ----
        const float4* rowp =
            reinterpret_cast<const float4*>(inputs + (size_t)row * DCOLS);
        float sq = 0.0f;
        #pragma unroll 4
        for (int i = tid; i < DCOLS / 4; i += NTHREADS) {
            float4 v = rowp[i];
            sq = fmaf(v.x, v.x, sq);
            sq = fmaf(v.y, v.y, sq);
            sq = fmaf(v.z, v.z, sq);
            sq = fmaf(v.w, v.w, sq);
        }
        // Linearity: fold W_i * (thread's partial sq); no row reduction.
        total = fmaf(W, sq, total);

        // ---- Gather term, once per row (warp 0 lanes 0..15; L2-hot) ----
        if (wid == 0 && lane < LGT) {
            const float g = __ldg(inputs + (size_t)row * DCOLS + c * LGT + lane);
            total = fmaf(w, 1.0f - 2.0f * g, total);
        }
    }

    // ---- Epilogue: one block reduce + one global atomic per CTA ----
    __shared__ float warp_sums[NTHREADS / 32];
    #pragma unroll
    for (int off = 16; off > 0; off >>= 1)
        total += __shfl_xor_sync(0xFFFFFFFFu, total, off);
    if (lane == 0) warp_sums[wid] = total;
    __syncthreads();

    if (tid < 32) {
        float v = warp_sums[tid];   // NTHREADS/32 == 32 exactly
        #pragma unroll
        for (int off = 16; off > 0; off >>= 1)
            v += __shfl_xor_sync(0xFFFFFFFFu, v, off);

        if (tid == 0) {
            atomicAdd(&g_acc, v);
            __threadfence();
            const unsigned done = atomicAdd(&g_cnt, 1u);
            if (done == NWORKERS - 1) {
                // All contributions visible (each CTA fenced before its
                // counter increment). Read + reset for the next graph replay.
                const float t = atomicExch(&g_acc, 0.0f);
                out[0] = t * (1.0f / (float)NROWS);
                g_cnt = 0u;
                __threadfence();
            }
        }
    }
}

extern "C" void kernel_launch(void* const* d_in, const int* in_sizes, int n_in,
                              void* d_out, int out_size) {
    const float* inputs = (const float*)d_in[0];
    const float* labels = (const float*)d_in[1];
    float* out = (float*)d_out;

    rvsml_loss_kernel<<<NWORKERS, NTHREADS>>>(inputs, labels, out);
}